// round 8
// baseline (speedup 1.0000x reference)
#include <cuda_runtime.h>
#include <cstdint>

#define KDIM   65536
#define MROWS  2048
#define NDFv   256
#define NCv    100
#define SPLITS 4
#define KPS    (KDIM / SPLITS)   // 16384
#define KC     128
#define NCHUNK (KPS / KC)        // 128
#define T16K   16384
#define OFF_AH 0
#define OFF_AL (1 * T16K)
#define OFF_AK (2 * T16K)
#define OFF_BH (3 * T16K)
#define OFF_BL (4 * T16K)
#define OFF_BK (5 * T16K)
#define STAGE  (6 * T16K)        // 98304
#define SMEM_TOTAL (2 * STAGE)   // 196608

// device-global scratch (no cudaMalloc allowed)
__device__ __align__(16) char g_A8h[(size_t)MROWS * KDIM];
__device__ __align__(16) char g_A8l[(size_t)MROWS * KDIM];
__device__ __align__(16) char g_A8k[(size_t)MROWS * KDIM];
__device__ __align__(16) char g_B8h[(size_t)NDFv * KDIM];
__device__ __align__(16) char g_B8l[(size_t)NDFv * KDIM];
__device__ __align__(16) char g_B8k[(size_t)NDFv * KDIM];
__device__ float g_sa[SPLITS * MROWS];
__device__ float g_sb[SPLITS * NDFv];
__device__ float g_bred[SPLITS * 64 * NDFv];
__device__ float g_partial[(size_t)SPLITS * MROWS * NDFv];

// ---------------- helpers (sm_80-class PTX only) ----------------------------
__device__ __forceinline__ uint32_t smem_u32(const void* p) {
    uint32_t a;
    asm("{ .reg .u64 t; cvta.to.shared.u64 t, %1; cvt.u32.u64 %0, t; }" : "=r"(a) : "l"(p));
    return a;
}
#define CP_ASYNC16(dst, src) \
    asm volatile("cp.async.cg.shared.global [%0], [%1], 16;" :: "r"(dst), "l"(src) : "memory")
#define CP_COMMIT() asm volatile("cp.async.commit_group;" ::: "memory")
#define CP_WAIT0()  asm volatile("cp.async.wait_group 0;" ::: "memory")
#define CP_WAIT1()  asm volatile("cp.async.wait_group 1;" ::: "memory")

__device__ __forceinline__ void ldsm4(uint32_t r[4], uint32_t a) {
    asm volatile("ldmatrix.sync.aligned.m8n8.x4.shared.b16 {%0,%1,%2,%3}, [%4];"
                 : "=r"(r[0]), "=r"(r[1]), "=r"(r[2]), "=r"(r[3]) : "r"(a));
}
__device__ __forceinline__ void imma16832(int d[4], const uint32_t a[4],
                                          uint32_t b0, uint32_t b1) {
    asm volatile("mma.sync.aligned.m16n8k32.row.col.s32.s8.s8.s32 "
                 "{%0,%1,%2,%3},{%4,%5,%6,%7},{%8,%9},{%0,%1,%2,%3};"
                 : "+r"(d[0]), "+r"(d[1]), "+r"(d[2]), "+r"(d[3])
                 : "r"(a[0]), "r"(a[1]), "r"(a[2]), "r"(a[3]), "r"(b0), "r"(b1));
}

#define KAPPA_INV (1.0f / 15.937f)   // kappa = sqrt(254)

// ---------------- A quantize: per (row, split) scale, 3 digit planes --------
__global__ __launch_bounds__(256) void aquant_kernel(const float* __restrict__ A) {
    const int row = blockIdx.x >> 2, split = blockIdx.x & 3;
    const int tid = threadIdx.x;
    const float4* src = (const float4*)(A + (size_t)row * KDIM + (size_t)split * KPS);
    float4 v[16];
    float m = 0.0f;
    #pragma unroll
    for (int i = 0; i < 16; i++) {
        v[i] = src[i * 256 + tid];
        m = fmaxf(m, fmaxf(fmaxf(fabsf(v[i].x), fabsf(v[i].y)),
                           fmaxf(fabsf(v[i].z), fabsf(v[i].w))));
    }
    #pragma unroll
    for (int o = 16; o > 0; o >>= 1) m = fmaxf(m, __shfl_xor_sync(0xffffffffu, m, o));
    __shared__ float red[8];
    if ((tid & 31) == 0) red[tid >> 5] = m;
    __syncthreads();
    if (tid == 0) {
        float t = red[0];
        #pragma unroll
        for (int i = 1; i < 8; i++) t = fmaxf(t, red[i]);
        red[0] = t;
    }
    __syncthreads();
    const float mx = red[0];
    const float inv = mx > 0.0f ? 127.0f / mx : 0.0f;
    const size_t base = (size_t)row * KDIM + (size_t)split * KPS;
    uint32_t* dh = (uint32_t*)(g_A8h + base);
    uint32_t* dl = (uint32_t*)(g_A8l + base);
    uint32_t* dk = (uint32_t*)(g_A8k + base);
    #pragma unroll
    for (int i = 0; i < 16; i++) {
        const float f[4] = { v[i].x, v[i].y, v[i].z, v[i].w };
        uint32_t ph = 0, pl = 0, pk = 0;
        #pragma unroll
        for (int j = 0; j < 4; j++) {
            const float x = f[j] * inv;
            const int qh = __float2int_rn(x);
            const float e = x - (float)qh;
            const int ql = __float2int_rn(e * 254.0f);
            const int qk = __float2int_rn((float)ql * KAPPA_INV);
            ph |= ((uint32_t)qh & 255u) << (8 * j);
            pl |= ((uint32_t)ql & 255u) << (8 * j);
            pk |= ((uint32_t)qk & 255u) << (8 * j);
        }
        dh[i * 256 + tid] = ph;
        dl[i * 256 + tid] = pl;
        dk[i * 256 + tid] = pk;
    }
    if (tid == 0) g_sa[split * MROWS + row] = mx * (1.0f / 127.0f);
}

// ---------------- B: column max (partial + final), then transpose+quantize --
__global__ __launch_bounds__(256) void bmaxp_kernel(const float* __restrict__ W) {
    const int split = blockIdx.x >> 6, slab = blockIdx.x & 63;
    const int n = threadIdx.x;
    const float* p = W + ((size_t)split * KPS + (size_t)slab * 256) * NDFv + n;
    float m = 0.0f;
    for (int r = 0; r < 256; r++) m = fmaxf(m, fabsf(p[(size_t)r * NDFv]));
    g_bred[blockIdx.x * NDFv + n] = m;
}
__global__ __launch_bounds__(256) void bmaxf_kernel() {
    const int split = blockIdx.x, n = threadIdx.x;
    float m = 0.0f;
    for (int s = 0; s < 64; s++) m = fmaxf(m, g_bred[(split * 64 + s) * NDFv + n]);
    g_sb[split * NDFv + n] = m * (1.0f / 127.0f);
}
__global__ __launch_bounds__(256) void bquant_kernel(const float* __restrict__ W) {
    __shared__ float tile[32][33];
    const int k0 = blockIdx.x * 32, n0 = blockIdx.y * 32;
    const int tx = threadIdx.x & 31, ty = threadIdx.x >> 5;
    #pragma unroll
    for (int i = 0; i < 4; i++)
        tile[ty * 4 + i][tx] = W[(size_t)(k0 + ty * 4 + i) * NDFv + n0 + tx];
    __syncthreads();
    const int split = k0 >> 14;   // KPS = 16384
    #pragma unroll
    for (int i = 0; i < 4; i++) {
        const int n = n0 + ty * 4 + i;
        const float sc = g_sb[split * NDFv + n];
        const float inv = sc > 0.0f ? 1.0f / sc : 0.0f;
        const float x = tile[tx][ty * 4 + i] * inv;
        const int qh = __float2int_rn(x);
        const float e = x - (float)qh;
        const int ql = __float2int_rn(e * 254.0f);
        const int qk = __float2int_rn((float)ql * KAPPA_INV);
        const size_t idx = (size_t)n * KDIM + k0 + tx;
        g_B8h[idx] = (char)qh;
        g_B8l[idx] = (char)ql;
        g_B8k[idx] = (char)qk;
    }
}

// ---------------- GEMM: int8 IMMA, 2-digit + kappa ll fold -------------------
#define ISSUE_CHUNK(c) do {                                                      \
    const uint32_t _st = sbase + (uint32_t)(((c) & 1) * STAGE);                  \
    _Pragma("unroll")                                                            \
    for (int j = 0; j < 4; j++) {                                                \
        const uint32_t o = drow + ((uint32_t)((lhalf * 4 + j) << 4) ^ xs);       \
        const size_t g = (size_t)(c) * KC + j * 16;                              \
        CP_ASYNC16(_st + OFF_AH + o, pAh + g);                                   \
        CP_ASYNC16(_st + OFF_AL + o, pAl + g);                                   \
        CP_ASYNC16(_st + OFF_AK + o, pAk + g);                                   \
        CP_ASYNC16(_st + OFF_BH + o, pBh + g);                                   \
        CP_ASYNC16(_st + OFF_BL + o, pBl + g);                                   \
        CP_ASYNC16(_st + OFF_BK + o, pBk + g);                                   \
    }                                                                            \
    CP_COMMIT();                                                                 \
} while (0)

__global__ __launch_bounds__(256, 1) void gemm_imma_kernel() {
    extern __shared__ char smem_dyn[];
    const uint32_t sbase = smem_u32(smem_dyn);
    const int tid = threadIdx.x;
    const int wid = tid >> 5, lane = tid & 31;
    const int mtile = blockIdx.x & 15;
    const int ntile = (blockIdx.x >> 4) & 1;
    const int split = blockIdx.x >> 5;
    const int wm = wid & 1, wn = wid >> 1;   // warp tile m64 x n32

    // loaders: 2 threads per 128B row
    const int lrow = tid >> 1, lhalf = tid & 1;
    const uint32_t xs = (uint32_t)((lrow & 7) << 4);
    const size_t a_go = (size_t)(mtile * 128 + lrow) * KDIM + (size_t)split * KPS + lhalf * 64;
    const size_t b_go = (size_t)(ntile * 128 + lrow) * KDIM + (size_t)split * KPS + lhalf * 64;
    const char* pAh = g_A8h + a_go;
    const char* pAl = g_A8l + a_go;
    const char* pAk = g_A8k + a_go;
    const char* pBh = g_B8h + b_go;
    const char* pBl = g_B8l + b_go;
    const char* pBk = g_B8k + b_go;
    const uint32_t drow = (uint32_t)(lrow * 128);

    // ldmatrix lane mapping (rows are 128B, kstep = 32B = 2 x 16B cols)
    const int a_r = (lane & 7) + ((lane >> 3) & 1) * 8;
    const uint32_t a_c16 = (uint32_t)(((lane >> 4) & 1) * 16);
    const uint32_t xf = (uint32_t)((a_r & 7) << 4);
    uint32_t colx[4];
    #pragma unroll
    for (int ks = 0; ks < 4; ks++) colx[ks] = (((uint32_t)ks << 5) | a_c16) ^ xf;

    int hh[4][4][4] = {};   // sum qh_a*qh_b
    int xx[4][4][4] = {};   // sum (qh_a*ql_b + ql_a*qh_b + qk_a*qk_b)

    ISSUE_CHUNK(0);

    for (int it = 0; it < NCHUNK; it++) {
        if (it + 1 < NCHUNK) { ISSUE_CHUNK(it + 1); CP_WAIT1(); }
        else                 { CP_WAIT0(); }
        __syncthreads();

        const uint32_t st = sbase + (uint32_t)((it & 1) * STAGE);
        #pragma unroll
        for (int ks = 0; ks < 4; ks++) {
            uint32_t ah[4][4], bh[2][4];
            #pragma unroll
            for (int mf = 0; mf < 4; mf++)
                ldsm4(ah[mf], st + OFF_AH + (uint32_t)((wm * 64 + mf * 16 + a_r) * 128) + colx[ks]);
            #pragma unroll
            for (int g = 0; g < 2; g++)
                ldsm4(bh[g], st + OFF_BH + (uint32_t)((wn * 32 + g * 16 + a_r) * 128) + colx[ks]);
            #pragma unroll
            for (int mf = 0; mf < 4; mf++)
                #pragma unroll
                for (int g = 0; g < 2; g++) {
                    imma16832(hh[mf][g * 2 + 0], ah[mf], bh[g][0], bh[g][2]);
                    imma16832(hh[mf][g * 2 + 1], ah[mf], bh[g][1], bh[g][3]);
                }
            uint32_t bl[2][4];
            #pragma unroll
            for (int g = 0; g < 2; g++)
                ldsm4(bl[g], st + OFF_BL + (uint32_t)((wn * 32 + g * 16 + a_r) * 128) + colx[ks]);
            #pragma unroll
            for (int mf = 0; mf < 4; mf++)
                #pragma unroll
                for (int g = 0; g < 2; g++) {
                    imma16832(xx[mf][g * 2 + 0], ah[mf], bl[g][0], bl[g][2]);
                    imma16832(xx[mf][g * 2 + 1], ah[mf], bl[g][1], bl[g][3]);
                }
            uint32_t al[4][4];
            #pragma unroll
            for (int mf = 0; mf < 4; mf++)
                ldsm4(al[mf], st + OFF_AL + (uint32_t)((wm * 64 + mf * 16 + a_r) * 128) + colx[ks]);
            #pragma unroll
            for (int mf = 0; mf < 4; mf++)
                #pragma unroll
                for (int g = 0; g < 2; g++) {
                    imma16832(xx[mf][g * 2 + 0], al[mf], bh[g][0], bh[g][2]);
                    imma16832(xx[mf][g * 2 + 1], al[mf], bh[g][1], bh[g][3]);
                }
            uint32_t ak[4][4], bk[2][4];
            #pragma unroll
            for (int mf = 0; mf < 4; mf++)
                ldsm4(ak[mf], st + OFF_AK + (uint32_t)((wm * 64 + mf * 16 + a_r) * 128) + colx[ks]);
            #pragma unroll
            for (int g = 0; g < 2; g++)
                ldsm4(bk[g], st + OFF_BK + (uint32_t)((wn * 32 + g * 16 + a_r) * 128) + colx[ks]);
            #pragma unroll
            for (int mf = 0; mf < 4; mf++)
                #pragma unroll
                for (int g = 0; g < 2; g++) {
                    imma16832(xx[mf][g * 2 + 0], ak[mf], bk[g][0], bk[g][2]);
                    imma16832(xx[mf][g * 2 + 1], ak[mf], bk[g][1], bk[g][3]);
                }
        }
        __syncthreads();
    }

    // epilogue: partial = sa*sb*(hh + xx/254)
    const float c254 = 1.0f / 254.0f;
    float* pb = g_partial + (size_t)split * MROWS * NDFv;
    #pragma unroll
    for (int mf = 0; mf < 4; mf++)
        #pragma unroll
        for (int nf = 0; nf < 4; nf++) {
            const int r0 = mtile * 128 + wm * 64 + mf * 16 + (lane >> 2);
            const int col = ntile * 128 + wn * 32 + nf * 8 + (lane & 3) * 2;
            const float sa0 = g_sa[split * MROWS + r0];
            const float sa1 = g_sa[split * MROWS + r0 + 8];
            const float sb0 = g_sb[split * NDFv + col];
            const float sb1 = g_sb[split * NDFv + col + 1];
            const float v0 = ((float)hh[mf][nf][0] + (float)xx[mf][nf][0] * c254) * sa0 * sb0;
            const float v1 = ((float)hh[mf][nf][1] + (float)xx[mf][nf][1] * c254) * sa0 * sb1;
            const float v2 = ((float)hh[mf][nf][2] + (float)xx[mf][nf][2] * c254) * sa1 * sb0;
            const float v3 = ((float)hh[mf][nf][3] + (float)xx[mf][nf][3] * c254) * sa1 * sb1;
            *(float2*)(pb + (size_t)r0 * NDFv + col) = make_float2(v0, v1);
            *(float2*)(pb + (size_t)(r0 + 8) * NDFv + col) = make_float2(v2, v3);
        }
}

// ---------------- split-K reduce ---------------------------------------------
__global__ __launch_bounds__(256) void reduce_kernel(const float* __restrict__ bias,
                                                     const int* __restrict__ mask,
                                                     float* __restrict__ zall) {
    const int i = blockIdx.x * 256 + threadIdx.x;   // float2 units
    const int row = i >> 7;
    const int col = (i & 127) * 2;
    float2 s = make_float2(0.f, 0.f);
    #pragma unroll
    for (int sp = 0; sp < SPLITS; sp++) {
        const float2 v = *(const float2*)&g_partial[(size_t)sp * MROWS * NDFv +
                                                    (size_t)row * NDFv + col];
        s.x += v.x; s.y += v.y;
    }
    const float m = mask[row] ? 1.0f : 0.0f;
    s.x = (s.x + bias[col]) * m;
    s.y = (s.y + bias[col + 1]) * m;
    *(float2*)&zall[(size_t)row * NDFv + col] = s;
}

// ---------------- student-t + normalize + argmax (2 rows / block) ------------
__global__ __launch_bounds__(128) void cluster_kernel(const float* __restrict__ Z,
                                                      const float* __restrict__ cent,
                                                      const int* __restrict__ mask,
                                                      float* __restrict__ S,
                                                      float* __restrict__ Cidx) {
    const int tid = threadIdx.x;
    const int row0 = blockIdx.x * 2;
    __shared__ __align__(16) float zs[2][256];
    __shared__ float stmp[2][128];
    __shared__ float red_s[2];
    __shared__ int   red_i[2];

    #pragma unroll
    for (int i = 0; i < 4; i++) {
        const int idx = i * 128 + tid;
        zs[idx >> 8][idx & 255] = Z[(size_t)row0 * 256 + idx];
    }
    __syncthreads();

    float v0 = 0.0f, v1 = 0.0f;
    if (tid < NCv) {
        const float4* c4 = (const float4*)(cent + (size_t)tid * NDFv);
        const float4* z0 = (const float4*)zs[0];
        const float4* z1 = (const float4*)zs[1];
        float d0 = 0.0f, d1 = 0.0f;
        #pragma unroll 8
        for (int j = 0; j < NDFv / 4; j++) {
            const float4 cv = c4[j];
            const float4 a = z0[j];
            const float4 b = z1[j];
            float dx = a.x - cv.x, dy = a.y - cv.y, dz = a.z - cv.z, dw = a.w - cv.w;
            d0 += dx * dx + dy * dy + dz * dz + dw * dw;
            dx = b.x - cv.x; dy = b.y - cv.y; dz = b.z - cv.z; dw = b.w - cv.w;
            d1 += dx * dx + dy * dy + dz * dz + dw * dw;
        }
        v0 = 1.0f / (1.0f + sqrtf(fmaxf(d0, 0.0f)));
        v1 = 1.0f / (1.0f + sqrtf(fmaxf(d1, 0.0f)));
    }
    stmp[0][tid] = v0;
    stmp[1][tid] = v1;
    __syncthreads();

    if (tid < 64) {
        const int r = tid >> 5, l = tid & 31;
        float sum = 0.0f, best = -1.0f;
        int bidx = 0;
        for (int k = l; k < NCv; k += 32) {
            const float v = stmp[r][k];
            sum += v;
            if (v > best) { best = v; bidx = k; }
        }
        #pragma unroll
        for (int off = 16; off > 0; off >>= 1) {
            sum += __shfl_down_sync(0xffffffffu, sum, off);
            const float ob = __shfl_down_sync(0xffffffffu, best, off);
            const int   oi = __shfl_down_sync(0xffffffffu, bidx, off);
            if (ob > best || (ob == best && oi < bidx)) { best = ob; bidx = oi; }
        }
        if (l == 0) { red_s[r] = sum; red_i[r] = bidx; }
    }
    __syncthreads();

    #pragma unroll
    for (int r = 0; r < 2; r++) {
        const int row = row0 + r;
        const bool m = mask[row] != 0;
        const float inv = m ? (1.0f / red_s[r]) : 0.0f;
        if (tid < NCv) S[(size_t)row * NCv + tid] = (r ? v1 : v0) * inv;
        if (tid == 0)  Cidx[row] = m ? (float)red_i[r] : 0.0f;
    }
}

// -----------------------------------------------------------------------------
extern "C" void kernel_launch(void* const* d_in, const int* in_sizes, int n_in,
                              void* d_out, int out_size) {
    (void)in_sizes; (void)n_in; (void)out_size;
    const float* z_roi = (const float*)d_in[0];
    const int*   mask  = (const int*)d_in[1];
    const float* w_emb = (const float*)d_in[2];
    const float* b_emb = (const float*)d_in[3];
    const float* cent  = (const float*)d_in[4];

    float* out  = (float*)d_out;
    float* zall = out;
    float* S    = out + (size_t)MROWS * NDFv;
    float* Cx   = S + (size_t)MROWS * NCv;

    cudaFuncSetAttribute(gemm_imma_kernel, cudaFuncAttributeMaxDynamicSharedMemorySize, SMEM_TOTAL);

    bmaxp_kernel<<<SPLITS * 64, 256>>>(w_emb);
    bmaxf_kernel<<<SPLITS, 256>>>();
    bquant_kernel<<<dim3(KDIM / 32, NDFv / 32), 256>>>(w_emb);
    aquant_kernel<<<MROWS * SPLITS, 256>>>(z_roi);
    gemm_imma_kernel<<<128, 256, SMEM_TOTAL>>>();
    reduce_kernel<<<(MROWS * NDFv / 2) / 256, 256>>>(b_emb, mask, zall);
    cluster_kernel<<<MROWS / 2, 128>>>(zall, cent, mask, S, Cx);
}

// round 9
// speedup vs baseline: 2.8619x; 2.8619x over previous
#include <cuda_runtime.h>
#include <cuda_fp16.h>
#include <cstdint>

#define KDIM   65536
#define MROWS  2048
#define NDFv   256
#define NCv    100
#define SPLITS 4
#define KPS    (KDIM / SPLITS)   // 16384
#define KC     64
#define NCHUNK (KPS / KC)        // 256
#define OFF_AH 0
#define OFF_AS 16384
#define OFF_BH 32768
#define OFF_BS 49152
#define STAGE  65536
#define SMEM_TOTAL (2 * STAGE)   // 128 KB

#define KAPPA     0.03125f       // 2^-5
#define KAPPA_INV 32.0f
#define ONE_MK    0.96875f       // 1 - kappa

// device-global scratch (no cudaMalloc allowed)
__device__ __align__(16) unsigned short g_Bh[(size_t)NDFv * KDIM]; // [n][k] fp16 rn(w)
__device__ __align__(16) unsigned short g_Bs[(size_t)NDFv * KDIM]; // [n][k] fp16 Bh+32*Bl
__device__ float g_partial[(size_t)SPLITS * MROWS * NDFv];         // [split][row][col]

// ---------------- helpers (sm_80-class PTX only: valid on compute_103) ------
__device__ __forceinline__ uint32_t smem_u32(const void* p) {
    uint32_t a;
    asm("{ .reg .u64 t; cvta.to.shared.u64 t, %1; cvt.u32.u64 %0, t; }" : "=r"(a) : "l"(p));
    return a;
}
__device__ __forceinline__ uint32_t packh2(float lo, float hi) { // low half = rn16(lo)
    uint32_t r;
    asm("cvt.rn.f16x2.f32 %0, %1, %2;" : "=r"(r) : "f"(hi), "f"(lo));
    return r;
}
#define STS64V(a, r0, r1) \
    asm volatile("st.shared.v2.b32 [%0], {%1,%2};" :: "r"(a), "r"(r0), "r"(r1) : "memory")
#define CP_ASYNC16(dst, src) \
    asm volatile("cp.async.cg.shared.global [%0], [%1], 16;" :: "r"(dst), "l"(src) : "memory")
#define CP_COMMIT() asm volatile("cp.async.commit_group;" ::: "memory")
#define CP_WAIT0()  asm volatile("cp.async.wait_group 0;" ::: "memory")

__device__ __forceinline__ void ldsm4(uint32_t r[4], uint32_t a) {
    asm volatile("ldmatrix.sync.aligned.m8n8.x4.shared.b16 {%0,%1,%2,%3}, [%4];"
                 : "=r"(r[0]), "=r"(r[1]), "=r"(r[2]), "=r"(r[3]) : "r"(a));
}
__device__ __forceinline__ void mmaf16(float d[4], const uint32_t a[4],
                                       uint32_t b0, uint32_t b1) {
    asm volatile("mma.sync.aligned.m16n8k16.row.col.f32.f16.f16.f32 "
                 "{%0,%1,%2,%3},{%4,%5,%6,%7},{%8,%9},{%0,%1,%2,%3};"
                 : "+f"(d[0]), "+f"(d[1]), "+f"(d[2]), "+f"(d[3])
                 : "r"(a[0]), "r"(a[1]), "r"(a[2]), "r"(a[3]), "r"(b0), "r"(b1));
}

// ---------------- prepass: W [K,256] fp32 -> g_Bh/g_Bs [256][K] fp16 --------
__global__ __launch_bounds__(256) void bprep_kernel(const float* __restrict__ W) {
    __shared__ float tile[32][33];
    const int k0 = blockIdx.x * 32, n0 = blockIdx.y * 32;
    const int tx = threadIdx.x & 31, ty = threadIdx.x >> 5;
    #pragma unroll
    for (int i = 0; i < 4; i++)
        tile[ty * 4 + i][tx] = W[(size_t)(k0 + ty * 4 + i) * NDFv + n0 + tx];
    __syncthreads();
    #pragma unroll
    for (int i = 0; i < 4; i++) {
        const int n = ty * 4 + i;
        const float w = tile[tx][n];
        const __half bh = __float2half_rn(w);
        const float bhf = __half2float(bh);
        const float bl = w - bhf;
        const __half bs = __float2half_rn(fmaf(KAPPA_INV, bl, bhf));
        const size_t idx = (size_t)(n0 + n) * KDIM + k0 + tx;
        g_Bh[idx] = *(const unsigned short*)&bh;
        g_Bs[idx] = *(const unsigned short*)&bs;
    }
}

// ---------------- GEMM: fp16 2-pass kappa split, CTA tile 128x128 -----------
__global__ __launch_bounds__(256, 1) void gemm_mma_kernel(const float* __restrict__ A) {
    extern __shared__ char smem_dyn[];
    const uint32_t sbase = smem_u32(smem_dyn);
    const int tid = threadIdx.x;
    const int wid = tid >> 5, lane = tid & 31;
    const int mtile = blockIdx.x & 15;
    const int ntile = (blockIdx.x >> 4) & 1;
    const int split = blockIdx.x >> 5;
    const int wm = wid & 1, wn = wid >> 1;   // warp tile: m64 x n32

    // A loader: 2 threads per row (128 rows), each 32 k = 8 float4
    const int arow = tid >> 1, ahalf = tid & 1;
    const uint32_t xa = (uint32_t)((arow & 7) << 4);
    const float* Ag = A + (size_t)(mtile * 128 + arow) * KDIM + (size_t)split * KPS + ahalf * 32;
    // B loader: 2 threads per n-row (128 rows of this ntile), each 32 k = 4 x 16B
    const unsigned short* Bhg = g_Bh + (size_t)(ntile * 128 + arow) * KDIM
                                + (size_t)split * KPS + ahalf * 32;
    const unsigned short* Bsg = g_Bs + (size_t)(ntile * 128 + arow) * KDIM
                                + (size_t)split * KPS + ahalf * 32;

    // ldmatrix lane mapping
    const int a_r = (lane & 7) + ((lane >> 3) & 1) * 8;
    const uint32_t a_c16 = (uint32_t)(((lane >> 4) & 1) * 16);
    const uint32_t xf = (uint32_t)((a_r & 7) << 4);
    uint32_t colx[4];
    #pragma unroll
    for (int ks = 0; ks < 4; ks++) colx[ks] = (((uint32_t)ks << 5) | a_c16) ^ xf;

    float acc1[4][4][4] = {};   // P1 = Ah*Bh
    float acc2[4][4][4] = {};   // P2 = As*Bs
    float4 a_ld[8];

    // prologue: chunk 0
    #pragma unroll
    for (int i = 0; i < 8; i++) a_ld[i] = *(const float4*)(Ag + i * 4);
    #pragma unroll
    for (int j = 0; j < 4; j++) {
        const uint32_t off = (uint32_t)(arow * 128) + ((((uint32_t)(ahalf * 4 + j)) << 4) ^ xa);
        CP_ASYNC16(sbase + OFF_BH + off, Bhg + j * 8);
        CP_ASYNC16(sbase + OFF_BS + off, Bsg + j * 8);
    }
    CP_COMMIT();

    for (int it = 0; it < NCHUNK; it++) {
        const uint32_t st = sbase + (uint32_t)((it & 1) * STAGE);

        // A: fp32 regs -> fp16 Ah / As planes -> swizzled STS
        #pragma unroll
        for (int i = 0; i < 8; i++) {
            const float4 f = a_ld[i];
            const uint32_t h0 = packh2(f.x, f.y);
            const uint32_t h1 = packh2(f.z, f.w);
            const float ahx = __half2float(*(const __half*)&h0);
            const float ahy = __half2float(((const __half*)&h0)[1]);
            const float ahz = __half2float(*(const __half*)&h1);
            const float ahw = __half2float(((const __half*)&h1)[1]);
            // As = rn16((a - Ah) + kappa*Ah) = rn16(a - (1-kappa)*Ah)
            const uint32_t s0 = packh2(fmaf(-ONE_MK, ahx, f.x), fmaf(-ONE_MK, ahy, f.y));
            const uint32_t s1 = packh2(fmaf(-ONE_MK, ahz, f.z), fmaf(-ONE_MK, ahw, f.w));
            const uint32_t off = (uint32_t)(arow * 128) +
                                 (((uint32_t)(ahalf * 64 + i * 8)) ^ xa);
            STS64V(st + OFF_AH + off, h0, h1);
            STS64V(st + OFF_AS + off, s0, s1);
        }
        CP_WAIT0();
        __syncthreads();

        // prefetch next chunk
        if (it + 1 < NCHUNK) {
            const float* Ap = Ag + (size_t)(it + 1) * KC;
            #pragma unroll
            for (int i = 0; i < 8; i++) a_ld[i] = *(const float4*)(Ap + i * 4);
            const uint32_t st2 = sbase + (uint32_t)(((it + 1) & 1) * STAGE);
            const unsigned short* Bhp = Bhg + (size_t)(it + 1) * KC;
            const unsigned short* Bsp = Bsg + (size_t)(it + 1) * KC;
            #pragma unroll
            for (int j = 0; j < 4; j++) {
                const uint32_t off = (uint32_t)(arow * 128) +
                                     ((((uint32_t)(ahalf * 4 + j)) << 4) ^ xa);
                CP_ASYNC16(st2 + OFF_BH + off, Bhp + j * 8);
                CP_ASYNC16(st2 + OFF_BS + off, Bsp + j * 8);
            }
            CP_COMMIT();
        }

        // tensor-core mainloop: 2 independent passes per k-step
        #pragma unroll
        for (int ks = 0; ks < 4; ks++) {
            uint32_t ah[4][4], bh[2][4];
            #pragma unroll
            for (int mf = 0; mf < 4; mf++)
                ldsm4(ah[mf], st + OFF_AH + (uint32_t)((wm * 64 + mf * 16 + a_r) * 128) + colx[ks]);
            #pragma unroll
            for (int g = 0; g < 2; g++)
                ldsm4(bh[g], st + OFF_BH + (uint32_t)((wn * 32 + g * 16 + a_r) * 128) + colx[ks]);
            #pragma unroll
            for (int mf = 0; mf < 4; mf++)
                #pragma unroll
                for (int g = 0; g < 2; g++) {
                    mmaf16(acc1[mf][g * 2 + 0], ah[mf], bh[g][0], bh[g][2]);
                    mmaf16(acc1[mf][g * 2 + 1], ah[mf], bh[g][1], bh[g][3]);
                }
            uint32_t as[4][4], bs[2][4];
            #pragma unroll
            for (int mf = 0; mf < 4; mf++)
                ldsm4(as[mf], st + OFF_AS + (uint32_t)((wm * 64 + mf * 16 + a_r) * 128) + colx[ks]);
            #pragma unroll
            for (int g = 0; g < 2; g++)
                ldsm4(bs[g], st + OFF_BS + (uint32_t)((wn * 32 + g * 16 + a_r) * 128) + colx[ks]);
            #pragma unroll
            for (int mf = 0; mf < 4; mf++)
                #pragma unroll
                for (int g = 0; g < 2; g++) {
                    mmaf16(acc2[mf][g * 2 + 0], as[mf], bs[g][0], bs[g][2]);
                    mmaf16(acc2[mf][g * 2 + 1], as[mf], bs[g][1], bs[g][3]);
                }
        }
    }

    // epilogue: partial = (1-kappa)*P1 + P2
    float* pbase = g_partial + (size_t)split * MROWS * NDFv;
    #pragma unroll
    for (int mf = 0; mf < 4; mf++)
        #pragma unroll
        for (int nf = 0; nf < 4; nf++) {
            const int row = mtile * 128 + wm * 64 + mf * 16 + (lane >> 2);
            const int col = ntile * 128 + wn * 32 + nf * 8 + (lane & 3) * 2;
            float* p = pbase + (size_t)row * NDFv + col;
            const float v0 = fmaf(ONE_MK, acc1[mf][nf][0], acc2[mf][nf][0]);
            const float v1 = fmaf(ONE_MK, acc1[mf][nf][1], acc2[mf][nf][1]);
            const float v2 = fmaf(ONE_MK, acc1[mf][nf][2], acc2[mf][nf][2]);
            const float v3 = fmaf(ONE_MK, acc1[mf][nf][3], acc2[mf][nf][3]);
            *(float2*)p = make_float2(v0, v1);
            *(float2*)(p + 8 * NDFv) = make_float2(v2, v3);
        }
}

// ---------------- split-K reduce: zall = (sum partials + bias) * mask -------
__global__ __launch_bounds__(256) void reduce_kernel(const float* __restrict__ bias,
                                                     const int* __restrict__ mask,
                                                     float* __restrict__ zall) {
    const int i = blockIdx.x * 256 + threadIdx.x;   // float2 units
    const int row = i >> 7;
    const int col = (i & 127) * 2;
    float2 s = make_float2(0.f, 0.f);
    #pragma unroll
    for (int sp = 0; sp < SPLITS; sp++) {
        const float2 v = *(const float2*)&g_partial[(size_t)sp * MROWS * NDFv +
                                                    (size_t)row * NDFv + col];
        s.x += v.x; s.y += v.y;
    }
    const float m = mask[row] ? 1.0f : 0.0f;
    s.x = (s.x + bias[col]) * m;
    s.y = (s.y + bias[col + 1]) * m;
    *(float2*)&zall[(size_t)row * NDFv + col] = s;
}

// ---------------- student-t + normalize + argmax (2 rows / block, ILP x2) ---
__global__ __launch_bounds__(128) void cluster_kernel(const float* __restrict__ Z,
                                                      const float* __restrict__ cent,
                                                      const int* __restrict__ mask,
                                                      float* __restrict__ S,
                                                      float* __restrict__ Cidx) {
    const int tid = threadIdx.x;
    const int row0 = blockIdx.x * 2;
    __shared__ __align__(16) float zs[2][256];
    __shared__ float stmp[2][128];
    __shared__ float red_s[2];
    __shared__ int   red_i[2];

    #pragma unroll
    for (int i = 0; i < 4; i++) {
        const int idx = i * 128 + tid;
        zs[idx >> 8][idx & 255] = Z[(size_t)row0 * 256 + idx];
    }
    __syncthreads();

    float v0 = 0.0f, v1 = 0.0f;
    if (tid < NCv) {
        const float4* c4 = (const float4*)(cent + (size_t)tid * NDFv);
        const float4* z0 = (const float4*)zs[0];
        const float4* z1 = (const float4*)zs[1];
        float d0 = 0.0f, d1 = 0.0f;
        #pragma unroll 8
        for (int j = 0; j < NDFv / 4; j++) {
            const float4 cv = c4[j];
            const float4 a = z0[j];
            const float4 b = z1[j];
            float dx = a.x - cv.x, dy = a.y - cv.y, dz = a.z - cv.z, dw = a.w - cv.w;
            d0 += dx * dx + dy * dy + dz * dz + dw * dw;
            dx = b.x - cv.x; dy = b.y - cv.y; dz = b.z - cv.z; dw = b.w - cv.w;
            d1 += dx * dx + dy * dy + dz * dz + dw * dw;
        }
        v0 = 1.0f / (1.0f + sqrtf(fmaxf(d0, 0.0f)));
        v1 = 1.0f / (1.0f + sqrtf(fmaxf(d1, 0.0f)));
    }
    stmp[0][tid] = v0;
    stmp[1][tid] = v1;
    __syncthreads();

    if (tid < 64) {
        const int r = tid >> 5, l = tid & 31;
        float sum = 0.0f, best = -1.0f;
        int bidx = 0;
        for (int k = l; k < NCv; k += 32) {
            const float v = stmp[r][k];
            sum += v;
            if (v > best) { best = v; bidx = k; }
        }
        #pragma unroll
        for (int off = 16; off > 0; off >>= 1) {
            sum += __shfl_down_sync(0xffffffffu, sum, off);
            const float ob = __shfl_down_sync(0xffffffffu, best, off);
            const int   oi = __shfl_down_sync(0xffffffffu, bidx, off);
            if (ob > best || (ob == best && oi < bidx)) { best = ob; bidx = oi; }
        }
        if (l == 0) { red_s[r] = sum; red_i[r] = bidx; }
    }
    __syncthreads();

    #pragma unroll
    for (int r = 0; r < 2; r++) {
        const int row = row0 + r;
        const bool m = mask[row] != 0;
        const float inv = m ? (1.0f / red_s[r]) : 0.0f;
        if (tid < NCv) S[(size_t)row * NCv + tid] = (r ? v1 : v0) * inv;
        if (tid == 0)  Cidx[row] = m ? (float)red_i[r] : 0.0f;
    }
}

// ---------------------------------------------------------------------------
extern "C" void kernel_launch(void* const* d_in, const int* in_sizes, int n_in,
                              void* d_out, int out_size) {
    (void)in_sizes; (void)n_in; (void)out_size;
    const float* z_roi = (const float*)d_in[0];
    const int*   mask  = (const int*)d_in[1];
    const float* w_emb = (const float*)d_in[2];
    const float* b_emb = (const float*)d_in[3];
    const float* cent  = (const float*)d_in[4];

    float* out  = (float*)d_out;
    float* zall = out;
    float* S    = out + (size_t)MROWS * NDFv;
    float* Cx   = S + (size_t)MROWS * NCv;

    cudaFuncSetAttribute(gemm_mma_kernel, cudaFuncAttributeMaxDynamicSharedMemorySize, SMEM_TOTAL);

    bprep_kernel<<<dim3(KDIM / 32, NDFv / 32), 256>>>(w_emb);
    gemm_mma_kernel<<<128, 256, SMEM_TOTAL>>>(z_roi);
    reduce_kernel<<<(MROWS * NDFv / 2) / 256, 256>>>(b_emb, mask, zall);
    cluster_kernel<<<MROWS / 2, 128>>>(zall, cent, mask, S, Cx);
}